// round 9
// baseline (speedup 1.0000x reference)
#include <cuda_runtime.h>
#include <cstdint>

#define C        128
#define KNB      16
#define M        16            // points per warp task
#define WARPS    6
#define THREADS  (WARPS*32)
#define NPTS     (8*4096)
#define NTASK    (NPTS/M)      // 2048
#define RS       132           // padded smem row stride (floats)
#define SM_WARP  (2*M*RS)      // sx + su, floats
#define SMEM_BYTES (WARPS*SM_WARP*4)   // 101376

// Weights pre-permuted into m16n8k8 tf32 B-fragment order:
//   idx(n, k) with k = k0*8 + tt:  ((n*16 + k0)*8) + (tt&3)*2 + (tt>>2)
// so thread (g,t) of n-block n0 loads float2 at ((n0*8+g)*16 + k0)*8 + 2t
// giving (b0, b1) = (W[n][k0*8+t], W[n][k0*8+t+4]).
__device__ float g_Bhi[C*C], g_Blo[C*C];   // W = fold * B^T (n=logit ch, k=input ch)
__device__ float g_Whi[C*C], g_Wlo[C*C];   // W = wv (n=output ch, k=input ch)

__device__ __forceinline__ uint32_t tf32hi(float x) {
    uint32_t r; asm("cvt.rna.tf32.f32 %0, %1;" : "=r"(r) : "f"(x)); return r;
}
__device__ __forceinline__ float ex2(float x) {
    float r; asm("ex2.approx.f32 %0, %1;" : "=f"(r) : "f"(x)); return r;
}
__device__ __forceinline__ float dot4(const float4 a, const float4 b) {
    float t = a.x * b.x;
    t = fmaf(a.y, b.y, t);
    t = fmaf(a.z, b.z, t);
    t = fmaf(a.w, b.w, t);
    return t;
}
__device__ __forceinline__ void mma8(float* d, const uint32_t* a,
                                     uint32_t b0, uint32_t b1) {
    asm volatile("mma.sync.aligned.m16n8k8.row.col.f32.tf32.tf32.f32 "
                 "{%0,%1,%2,%3}, {%4,%5,%6,%7}, {%8,%9}, {%0,%1,%2,%3};"
                 : "+f"(d[0]), "+f"(d[1]), "+f"(d[2]), "+f"(d[3])
                 : "r"(a[0]), "r"(a[1]), "r"(a[2]), "r"(a[3]),
                   "r"(b0), "r"(b1));
}

__global__ void precompute_kernel(const float* __restrict__ wq,
                                  const float* __restrict__ wk,
                                  const float* __restrict__ wv) {
    const int i = blockIdx.x;   // input channel (k)
    const int j = threadIdx.x;  // output channel (n)
    float acc = 0.f;
#pragma unroll
    for (int o = 0; o < 64; ++o)
        acc = fmaf(wq[o*C + i], wk[o*C + j], acc);
    acc *= (0.125f * 1.4426950408889634f);     // fold softmax scale + log2(e)

    const int tt  = i & 7;
    const int idx = ((j*16 + (i >> 3)) << 3) + (tt & 3)*2 + (tt >> 2);

    const uint32_t bh = tf32hi(acc);
    g_Bhi[idx] = __uint_as_float(bh);
    g_Blo[idx] = acc - __uint_as_float(bh);
    const float w = wv[j*C + i];
    const uint32_t wh = tf32hi(w);
    g_Whi[idx] = __uint_as_float(wh);
    g_Wlo[idx] = w - __uint_as_float(wh);
}

// 3xTF32 GEMM: D[16 x 128] = A[16 x 128] * W[128 x 128]^T
// A rows in smem (stride RS), weights in fragment-permuted layout,
// result fragments stored to smem (stride RS).
__device__ __forceinline__ void gemm16(const float* __restrict__ sa,
                                       float* __restrict__ sd,
                                       const float* __restrict__ whi,
                                       const float* __restrict__ wlo,
                                       int g, int t) {
    float acc[16][4];
#pragma unroll
    for (int n = 0; n < 16; ++n)
#pragma unroll
        for (int q = 0; q < 4; ++q) acc[n][q] = 0.f;

#pragma unroll 1
    for (int k0 = 0; k0 < 16; ++k0) {
        // A fragment (tf32 m16n8k8): a0=(g,t) a1=(g+8,t) a2=(g,t+4) a3=(g+8,t+4)
        const float a0 = sa[g*RS     + k0*8 + t];
        const float a1 = sa[(g+8)*RS + k0*8 + t];
        const float a2 = sa[g*RS     + k0*8 + t + 4];
        const float a3 = sa[(g+8)*RS + k0*8 + t + 4];
        uint32_t ah[4], al[4];
        ah[0] = tf32hi(a0); ah[1] = tf32hi(a1);
        ah[2] = tf32hi(a2); ah[3] = tf32hi(a3);
        al[0] = __float_as_uint(a0 - __uint_as_float(ah[0]));
        al[1] = __float_as_uint(a1 - __uint_as_float(ah[1]));
        al[2] = __float_as_uint(a2 - __uint_as_float(ah[2]));
        al[3] = __float_as_uint(a3 - __uint_as_float(ah[3]));

#pragma unroll
        for (int n0 = 0; n0 < 16; ++n0) {
            const size_t wb = (size_t)(((n0*8 + g)*16 + k0) << 3) + 2*t;
            const float2 bh = *(const float2*)(whi + wb);
            const float2 bl = *(const float2*)(wlo + wb);
            const uint32_t bh0 = __float_as_uint(bh.x);
            const uint32_t bh1 = __float_as_uint(bh.y);
            mma8(acc[n0], ah, bh0, bh1);
            mma8(acc[n0], al, bh0, bh1);
            mma8(acc[n0], ah, __float_as_uint(bl.x), __float_as_uint(bl.y));
        }
    }
    // C fragment: c0=(g,2t) c1=(g,2t+1) c2=(g+8,2t) c3=(g+8,2t+1) per n-block
#pragma unroll
    for (int n0 = 0; n0 < 16; ++n0) {
        *(float2*)(sd + g*RS     + n0*8 + 2*t) = make_float2(acc[n0][0], acc[n0][1]);
        *(float2*)(sd + (g+8)*RS + n0*8 + 2*t) = make_float2(acc[n0][2], acc[n0][3]);
    }
}

__global__ void __launch_bounds__(THREADS, 2)
attn_kernel(const float* __restrict__ fc,   // [NPTS][C]
            const float* __restrict__ fn,   // [NPTS][KNB][C]
            float* __restrict__ outp)       // [NPTS][C]
{
    extern __shared__ float dsm[];
    const int warp = threadIdx.x >> 5;
    const int lane = threadIdx.x & 31;
    const int task = blockIdx.x * WARPS + warp;
    if (task >= NTASK) return;
    const int p0 = task * M;
    const int g = lane >> 2, t = lane & 3;
    const int l4 = lane * 4;

    float* sx = dsm + warp * SM_WARP;      // X tile, later Y tile
    float* su = sx + M*RS;                 // U tile, later Out tile

    // ---- stage center features ----
#pragma unroll
    for (int it = 0; it < M; ++it)
        *(float4*)(sx + it*RS + l4) =
            *(const float4*)(fc + (size_t)(p0 + it)*C + l4);
    __syncwarp();

    // ---- GEMM-A: U = X * B^T (3xTF32) ----
    gemm16(sx, su, g_Bhi, g_Blo, g, t);
    __syncwarp();

    // ---- middle: per point softmax over {16 neighbors, center} ----
#pragma unroll 1
    for (int p = 0; p < M; ++p) {
        const float4 u4 = *(const float4*)(su + p*RS + l4);
        const float4 c4 = *(const float4*)(sx + p*RS + l4);
        const float* xn = fn + (size_t)(p0 + p)*(KNB*C) + l4;

        float4 xr[KNB];
#pragma unroll
        for (int j = 0; j < KNB; ++j)
            xr[j] = *(const float4*)(xn + j*C);

        float d[KNB + 1];
#pragma unroll
        for (int j = 0; j < KNB; ++j) d[j] = dot4(u4, xr[j]);
        d[KNB] = dot4(u4, c4);
#pragma unroll
        for (int off = 16; off; off >>= 1)
#pragma unroll
            for (int q = 0; q <= KNB; ++q)
                d[q] += __shfl_xor_sync(0xffffffffu, d[q], off);

        float m = d[0];
#pragma unroll
        for (int q = 1; q <= KNB; ++q) m = fmaxf(m, d[q]);
        const float wc = ex2(d[KNB] - m);
        float s = wc;
        float4 y;
        y.x = wc*c4.x; y.y = wc*c4.y; y.z = wc*c4.z; y.w = wc*c4.w;
#pragma unroll
        for (int j = 0; j < KNB; ++j) {
            const float w = ex2(d[j] - m);
            s += w;
            y.x = fmaf(w, xr[j].x, y.x);
            y.y = fmaf(w, xr[j].y, y.y);
            y.z = fmaf(w, xr[j].z, y.z);
            y.w = fmaf(w, xr[j].w, y.w);
        }
        const float rs = __fdividef(1.f, s);
        y.x *= rs; y.y *= rs; y.z *= rs; y.w *= rs;
        *(float4*)(sx + p*RS + l4) = y;    // overwrite X row with Y row
    }
    __syncwarp();

    // ---- GEMM-C: Out = Y * wv^T (3xTF32), result into su ----
    gemm16(sx, su, g_Whi, g_Wlo, g, t);
    __syncwarp();

    // ---- coalesced store ----
#pragma unroll
    for (int it = 0; it < M; ++it)
        *(float4*)(outp + (size_t)(p0 + it)*C + l4) =
            *(const float4*)(su + it*RS + l4);
}

extern "C" void kernel_launch(void* const* d_in, const int* in_sizes, int n_in,
                              void* d_out, int out_size) {
    const float* fc = (const float*)d_in[0];   // fea_center [8,4096,1,128]
    const float* fn = (const float*)d_in[1];   // fea_near   [8,4096,16,128]
    const float* wq = (const float*)d_in[2];   // [64,128]
    const float* wk = (const float*)d_in[3];   // [64,128]
    const float* wv = (const float*)d_in[4];   // [128,128]
    float* out = (float*)d_out;                // [8,4096,128]

    cudaFuncSetAttribute(attn_kernel,
                         cudaFuncAttributeMaxDynamicSharedMemorySize, SMEM_BYTES);
    precompute_kernel<<<C, C>>>(wq, wk, wv);
    const int blocks = (NTASK + WARPS - 1) / WARPS;   // 342
    attn_kernel<<<blocks, THREADS, SMEM_BYTES>>>(fc, fn, out);
}

// round 10
// speedup vs baseline: 1.6261x; 1.6261x over previous
#include <cuda_runtime.h>
#include <cstdint>

#define C        128
#define KNB      16
#define M        16            // points per warp task
#define WARPS    6
#define THREADS  (WARPS*32)
#define NPTS     (8*4096)
#define NTASK    (NPTS/M)      // 2048
#define RS       132           // padded smem row stride (floats)
#define SM_WARP  (2*M*RS)      // sx + su, floats
#define SMEM_BYTES (WARPS*SM_WARP*4)   // 101376

// Warp-blocked MMA fragment weight layout (m16n8k8 tf32):
// float4 at [(n0*16 + k0)*32 + lane]  (lane = g*4 + t) holds
//   .x = hi(W[n0*8+g][k0*8+t])    .y = hi(W[n0*8+g][k0*8+t+4])
//   .z = lo(...t)                 .w = lo(...t+4)
// One warp-wide LDG.128 = 512B contiguous = the whole (n0,k0) B-fragment.
__device__ float4 g_Bf[C*C/2];   // W = fold * B^T (n=logit ch, k=input ch), 128KB
__device__ float4 g_Wf[C*C/2];   // W = wv (n=output ch, k=input ch), 128KB

__device__ __forceinline__ uint32_t tf32hi(float x) {
    uint32_t r; asm("cvt.rna.tf32.f32 %0, %1;" : "=r"(r) : "f"(x)); return r;
}
__device__ __forceinline__ float ex2(float x) {
    float r; asm("ex2.approx.f32 %0, %1;" : "=f"(r) : "f"(x)); return r;
}
__device__ __forceinline__ float dot4(const float4 a, const float4 b) {
    float t = a.x * b.x;
    t = fmaf(a.y, b.y, t);
    t = fmaf(a.z, b.z, t);
    t = fmaf(a.w, b.w, t);
    return t;
}
__device__ __forceinline__ void mma8(float* d, const uint32_t* a,
                                     uint32_t b0, uint32_t b1) {
    asm volatile("mma.sync.aligned.m16n8k8.row.col.f32.tf32.tf32.f32 "
                 "{%0,%1,%2,%3}, {%4,%5,%6,%7}, {%8,%9}, {%0,%1,%2,%3};"
                 : "+f"(d[0]), "+f"(d[1]), "+f"(d[2]), "+f"(d[3])
                 : "r"(a[0]), "r"(a[1]), "r"(a[2]), "r"(a[3]),
                   "r"(b0), "r"(b1));
}

__global__ void precompute_kernel(const float* __restrict__ wq,
                                  const float* __restrict__ wk,
                                  const float* __restrict__ wv) {
    const int i = blockIdx.x;   // input channel (k)
    const int j = threadIdx.x;  // output channel (n)
    float acc = 0.f;
#pragma unroll
    for (int o = 0; o < 64; ++o)
        acc = fmaf(wq[o*C + i], wk[o*C + j], acc);
    acc *= (0.125f * 1.4426950408889634f);     // fold softmax scale + log2(e)

    const int n0 = j >> 3, g = j & 7;
    const int k0 = i >> 3, kk = i & 7;
    const int t  = kk & 3, pos = kk >> 2;      // pos 0 -> (x,z), 1 -> (y,w)
    const int base = (((n0*16 + k0)*32) + (g*4 + t)) * 4;

    const uint32_t bh = tf32hi(acc);
    ((float*)g_Bf)[base + pos]     = __uint_as_float(bh);
    ((float*)g_Bf)[base + 2 + pos] = acc - __uint_as_float(bh);
    const float w = wv[j*C + i];
    const uint32_t wh = tf32hi(w);
    ((float*)g_Wf)[base + pos]     = __uint_as_float(wh);
    ((float*)g_Wf)[base + 2 + pos] = w - __uint_as_float(wh);
}

// 3xTF32 GEMM: D[16 x 128] = A[16 x 128] * W[128 x 128]^T
// A rows in smem (stride RS), weights warp-blocked, result to smem.
__device__ __forceinline__ void gemm16(const float* __restrict__ sa,
                                       float* __restrict__ sd,
                                       const float4* __restrict__ wf,
                                       int g, int t, int lane) {
    float acc[16][4];
#pragma unroll
    for (int n = 0; n < 16; ++n)
#pragma unroll
        for (int q = 0; q < 4; ++q) acc[n][q] = 0.f;

#pragma unroll 1
    for (int k0 = 0; k0 < 16; ++k0) {
        // A fragment (tf32 m16n8k8): a0=(g,t) a1=(g+8,t) a2=(g,t+4) a3=(g+8,t+4)
        const float a0 = sa[g*RS     + k0*8 + t];
        const float a1 = sa[(g+8)*RS + k0*8 + t];
        const float a2 = sa[g*RS     + k0*8 + t + 4];
        const float a3 = sa[(g+8)*RS + k0*8 + t + 4];
        uint32_t ah[4], al[4];
        ah[0] = tf32hi(a0); ah[1] = tf32hi(a1);
        ah[2] = tf32hi(a2); ah[3] = tf32hi(a3);
        al[0] = __float_as_uint(a0 - __uint_as_float(ah[0]));
        al[1] = __float_as_uint(a1 - __uint_as_float(ah[1]));
        al[2] = __float_as_uint(a2 - __uint_as_float(ah[2]));
        al[3] = __float_as_uint(a3 - __uint_as_float(ah[3]));

        const float4* wp = wf + k0*32 + lane;
#pragma unroll
        for (int n0 = 0; n0 < 16; ++n0) {
            const float4 b = wp[n0*512];          // one LDG.128, warp-contiguous
            const uint32_t bh0 = __float_as_uint(b.x);
            const uint32_t bh1 = __float_as_uint(b.y);
            mma8(acc[n0], ah, bh0, bh1);
            mma8(acc[n0], al, bh0, bh1);
            mma8(acc[n0], ah, __float_as_uint(b.z), __float_as_uint(b.w));
        }
    }
    // C fragment: c0=(g,2t) c1=(g,2t+1) c2=(g+8,2t) c3=(g+8,2t+1) per n-block
#pragma unroll
    for (int n0 = 0; n0 < 16; ++n0) {
        *(float2*)(sd + g*RS     + n0*8 + 2*t) = make_float2(acc[n0][0], acc[n0][1]);
        *(float2*)(sd + (g+8)*RS + n0*8 + 2*t) = make_float2(acc[n0][2], acc[n0][3]);
    }
}

__global__ void __launch_bounds__(THREADS, 2)
attn_kernel(const float* __restrict__ fc,   // [NPTS][C]
            const float* __restrict__ fn,   // [NPTS][KNB][C]
            float* __restrict__ outp)       // [NPTS][C]
{
    extern __shared__ float dsm[];
    const int warp = threadIdx.x >> 5;
    const int lane = threadIdx.x & 31;
    const int task = blockIdx.x * WARPS + warp;
    if (task >= NTASK) return;
    const int p0 = task * M;
    const int g = lane >> 2, t = lane & 3;
    const int l4 = lane * 4;

    float* sx = dsm + warp * SM_WARP;      // X tile, later Y tile
    float* su = sx + M*RS;                 // U tile, later Out tile

    // ---- stage center features ----
#pragma unroll
    for (int it = 0; it < M; ++it)
        *(float4*)(sx + it*RS + l4) =
            *(const float4*)(fc + (size_t)(p0 + it)*C + l4);
    __syncwarp();

    // ---- GEMM-A: U = X * B^T (3xTF32) ----
    gemm16(sx, su, g_Bf, g, t, lane);
    __syncwarp();

    // ---- middle: per point softmax over {16 neighbors, center} ----
#pragma unroll 1
    for (int p = 0; p < M; ++p) {
        const float4 u4 = *(const float4*)(su + p*RS + l4);
        const float4 c4 = *(const float4*)(sx + p*RS + l4);
        const float* xn = fn + (size_t)(p0 + p)*(KNB*C) + l4;

        float4 xr[KNB];
#pragma unroll
        for (int j = 0; j < KNB; ++j)
            xr[j] = *(const float4*)(xn + j*C);

        float d[KNB + 1];
#pragma unroll
        for (int j = 0; j < KNB; ++j) d[j] = dot4(u4, xr[j]);
        d[KNB] = dot4(u4, c4);
#pragma unroll
        for (int off = 16; off; off >>= 1)
#pragma unroll
            for (int q = 0; q <= KNB; ++q)
                d[q] += __shfl_xor_sync(0xffffffffu, d[q], off);

        float m = d[0];
#pragma unroll
        for (int q = 1; q <= KNB; ++q) m = fmaxf(m, d[q]);
        const float wc = ex2(d[KNB] - m);
        float s = wc;
        float4 y;
        y.x = wc*c4.x; y.y = wc*c4.y; y.z = wc*c4.z; y.w = wc*c4.w;
#pragma unroll
        for (int j = 0; j < KNB; ++j) {
            const float w = ex2(d[j] - m);
            s += w;
            y.x = fmaf(w, xr[j].x, y.x);
            y.y = fmaf(w, xr[j].y, y.y);
            y.z = fmaf(w, xr[j].z, y.z);
            y.w = fmaf(w, xr[j].w, y.w);
        }
        const float rs = __fdividef(1.f, s);
        y.x *= rs; y.y *= rs; y.z *= rs; y.w *= rs;
        *(float4*)(sx + p*RS + l4) = y;    // overwrite X row with Y row
    }
    __syncwarp();

    // ---- GEMM-C: Out = Y * wv^T (3xTF32), result into su ----
    gemm16(sx, su, g_Wf, g, t, lane);
    __syncwarp();

    // ---- coalesced store ----
#pragma unroll
    for (int it = 0; it < M; ++it)
        *(float4*)(outp + (size_t)(p0 + it)*C + l4) =
            *(const float4*)(su + it*RS + l4);
}

extern "C" void kernel_launch(void* const* d_in, const int* in_sizes, int n_in,
                              void* d_out, int out_size) {
    const float* fc = (const float*)d_in[0];   // fea_center [8,4096,1,128]
    const float* fn = (const float*)d_in[1];   // fea_near   [8,4096,16,128]
    const float* wq = (const float*)d_in[2];   // [64,128]
    const float* wk = (const float*)d_in[3];   // [64,128]
    const float* wv = (const float*)d_in[4];   // [128,128]
    float* out = (float*)d_out;                // [8,4096,128]

    cudaFuncSetAttribute(attn_kernel,
                         cudaFuncAttributeMaxDynamicSharedMemorySize, SMEM_BYTES);
    precompute_kernel<<<C, C>>>(wq, wk, wv);
    const int blocks = (NTASK + WARPS - 1) / WARPS;   // 342
    attn_kernel<<<blocks, THREADS, SMEM_BYTES>>>(fc, fn, out);
}